// round 13
// baseline (speedup 1.0000x reference)
#include <cuda_runtime.h>
#include <cuda_fp16.h>
#include <math.h>
#include <stdint.h>

// ---------------- problem dims ----------------
#define BB   16
#define NQ   32
#define NN   128
#define TT   352
#define DD   768
#define HH   8
#define LL   512
#define HD   96
#define FF   3072
#define NLAY 6
#define ROWS (BB*LL)          // 8192
#define TS   (NQ+NN)          // 160 text start

// ---------------- scratch (static device globals; no allocs) ----------------
__device__ float  g_x[ROWS*DD];            // fp32 activations
__device__ float  g_y[ROWS*DD];            // fp32 gemm output (AO/FF2/gproj)
__device__ __half g_x16[ROWS*DD];          // fp16 activations (GEMM A side)
__device__ __half g_qkv16[ROWS*3*DD];      // fp16 qkv
__device__ __half g_ctx16[ROWS*DD];        // fp16 attn context
__device__ __half g_h16[ROWS*FF];          // fp16 ffn hidden
__device__ __half g_gnf16[BB*NN*DD];       // fp16 graph node features
// fp16 transposed weights
#define WT_QKV   0L
#define WT_AO    (WT_QKV + 6L*2304*768)
#define WT_FF1   (WT_AO  + 6L*768*768)
#define WT_FF2   (WT_FF1 + 6L*3072*768)
#define WT_GP    (WT_FF2 + 6L*768*3072)
#define WT_TOTAL (WT_GP + 768L*768)
__device__ __half g_w16[WT_TOTAL];

// ================= helpers =================
__device__ __forceinline__ uint32_t smem_u32(const void* p) {
    uint32_t a;
    asm("{ .reg .u64 t; cvta.to.shared.u64 t, %1; cvt.u32.u64 %0, t; }" : "=r"(a) : "l"(p));
    return a;
}
__device__ __forceinline__ uint32_t swz128(uint32_t off) { return off ^ ((off >> 3) & 0x70); }
__device__ __forceinline__ uint32_t swz64(uint32_t off)  { return off ^ ((off >> 3) & 0x30); }
__device__ __forceinline__ uint32_t packh2(float a, float b) {
    __half2 h = __floats2half2_rn(a, b);
    return *(uint32_t*)&h;
}
#define CP_ASYNC16(s, g) \
    asm volatile("cp.async.ca.shared.global [%0], [%1], 16;" :: "r"(s), "l"(g))
#define CP_COMMIT() asm volatile("cp.async.commit_group;" ::: "memory")
#define CP_WAIT1()  asm volatile("cp.async.wait_group 1;" ::: "memory")
#define CP_WAIT0()  asm volatile("cp.async.wait_group 0;" ::: "memory")
#define LDSM_X4(r0, r1, r2, r3, addr) \
    asm volatile("ldmatrix.sync.aligned.m8n8.x4.shared.b16 {%0,%1,%2,%3}, [%4];" \
        : "=r"(r0), "=r"(r1), "=r"(r2), "=r"(r3) : "r"(addr))
#define LDSM_X4_T(r0, r1, r2, r3, addr) \
    asm volatile("ldmatrix.sync.aligned.m8n8.x4.trans.shared.b16 {%0,%1,%2,%3}, [%4];" \
        : "=r"(r0), "=r"(r1), "=r"(r2), "=r"(r3) : "r"(addr))
// fp16 mma m16n8k16: a0..a3 (m16 x k16), b0,b1 (k16 x n8), fp32 accum
#define MMA_F16(c0, c1, c2, c3, a0, a1, a2, a3, b0, b1) \
    asm volatile("mma.sync.aligned.m16n8k16.row.col.f32.f16.f16.f32 " \
        "{%0,%1,%2,%3}, {%4,%5,%6,%7}, {%8,%9}, {%0,%1,%2,%3};" \
        : "+f"(c0), "+f"(c1), "+f"(c2), "+f"(c3) \
        : "r"(a0), "r"(a1), "r"(a2), "r"(a3), "r"(b0), "r"(b1))

#define GSTAGE 32768                   // A 16KB + B 16KB (128 rows x 64 halves each)
#define GSMEM_BYTES (3 * GSTAGE)

// flash smem: 3 K slots (16KB SW128 d0-63 + 8KB SW64 d64-95) + 3 V slots (128x208B) + keep flags
#define KSLOT 24576
#define VSLOT 26624
#define VSTRIDE 208
#define FV_OFF (3 * KSLOT)                       // 73728
#define FKEEP_OFF (FV_OFF + 3 * VSLOT)           // 153600
#define FSMEM_BYTES (FKEEP_OFF + 512)            // 154112

// ============ fp16 mma GEMM: C[M,N] = A[M,K] @ Bt[N,K]^T + bias ============
// BM=BN=128, BK=64 halves, 256 threads (2x4 warps), 3-stage cp.async pipeline.
__global__ void __launch_bounds__(256) tc_gemm_h(
    const __half* __restrict__ A, const __half* __restrict__ Bt,
    const float* __restrict__ bias, float* __restrict__ C32,
    __half* __restrict__ C16, int M, int N, int K, int act)
{
    extern __shared__ char smem[];
    const uint32_t sb = smem_u32(smem);
    const int tid = threadIdx.x;
    const int wid = tid >> 5, lane = tid & 31;
    const int wr = wid >> 2, wc = wid & 3;
    const int mBase = blockIdx.y * 128, nBase = blockIdx.x * 128;
    const int KT = K >> 6;

    float acc[4][4][4];
#pragma unroll
    for (int mi = 0; mi < 4; ++mi)
#pragma unroll
        for (int ni = 0; ni < 4; ++ni)
#pragma unroll
            for (int r = 0; r < 4; ++r) acc[mi][ni][r] = 0.f;

#pragma unroll
    for (int s = 0; s < 2; ++s) {
        const long koff = (long)s * 64;
        const uint32_t st = sb + s * GSTAGE;
#pragma unroll
        for (int i = 0; i < 4; ++i) {
            int g = tid + i * 256, row = g >> 3, seg = g & 7;
            uint32_t ds = swz128(row * 128 + seg * 16);
            CP_ASYNC16(st + ds,         A  + (long)(mBase + row) * K + koff + seg * 8);
            CP_ASYNC16(st + 16384 + ds, Bt + (long)(nBase + row) * K + koff + seg * 8);
        }
        CP_COMMIT();
    }

    const int a_row = (lane & 7) + ((lane >> 3) & 1) * 8;
    const int a_seg = ((lane >> 4) & 1) * 16;
    const int b_row = (lane & 7) + ((lane >> 4) & 1) * 8;
    const int b_seg = ((lane >> 3) & 1) * 16;

    for (int j = 0; j < KT; ++j) {
        if (j == KT - 1) { CP_WAIT0(); } else { CP_WAIT1(); }
        __syncthreads();
        if (j + 2 < KT) {
            const long koff = (long)(j + 2) * 64;
            const uint32_t st = sb + ((j + 2) % 3) * GSTAGE;
#pragma unroll
            for (int i = 0; i < 4; ++i) {
                int g = tid + i * 256, row = g >> 3, seg = g & 7;
                uint32_t ds = swz128(row * 128 + seg * 16);
                CP_ASYNC16(st + ds,         A  + (long)(mBase + row) * K + koff + seg * 8);
                CP_ASYNC16(st + 16384 + ds, Bt + (long)(nBase + row) * K + koff + seg * 8);
            }
            CP_COMMIT();
        }
        const uint32_t As = sb + (j % 3) * GSTAGE;
        const uint32_t Bs = As + 16384;
#pragma unroll
        for (int kk = 0; kk < 4; ++kk) {
            uint32_t a[4][4], b[2][4];
#pragma unroll
            for (int mi = 0; mi < 4; ++mi) {
                int row = wr * 64 + mi * 16 + a_row;
                LDSM_X4(a[mi][0], a[mi][1], a[mi][2], a[mi][3],
                        As + swz128(row * 128 + kk * 32 + a_seg));
            }
#pragma unroll
            for (int nb = 0; nb < 2; ++nb) {
                int row = wc * 32 + nb * 16 + b_row;
                LDSM_X4(b[nb][0], b[nb][1], b[nb][2], b[nb][3],
                        Bs + swz128(row * 128 + kk * 32 + b_seg));
            }
#pragma unroll
            for (int mi = 0; mi < 4; ++mi)
#pragma unroll
                for (int ni = 0; ni < 4; ++ni) {
                    int nb = ni >> 1, p = (ni & 1) * 2;
                    MMA_F16(acc[mi][ni][0], acc[mi][ni][1], acc[mi][ni][2], acc[mi][ni][3],
                            a[mi][0], a[mi][1], a[mi][2], a[mi][3],
                            b[nb][p], b[nb][p + 1]);
                }
        }
    }

    const int g4 = lane >> 2, t4 = lane & 3;
#pragma unroll
    for (int mi = 0; mi < 4; ++mi) {
#pragma unroll
        for (int r2 = 0; r2 < 2; ++r2) {
            int row = mBase + wr * 64 + mi * 16 + g4 + r2 * 8;
            const float* bp = bias + nBase + wc * 32;
#pragma unroll
            for (int ni = 0; ni < 4; ++ni) {
                int col = ni * 8 + t4 * 2;
                float v0 = acc[mi][ni][r2 * 2 + 0] + bp[col];
                float v1 = acc[mi][ni][r2 * 2 + 1] + bp[col + 1];
                if (act == 1) {
                    v0 = 0.5f * v0 * (1.0f + erff(v0 * 0.70710678118654752f));
                    v1 = 0.5f * v1 * (1.0f + erff(v1 * 0.70710678118654752f));
                }
                if (C16) {
                    *(__half2*)(C16 + (long)row * N + nBase + wc * 32 + col) =
                        __floats2half2_rn(v0, v1);
                } else {
                    *(float2*)(C32 + (long)row * N + nBase + wc * 32 + col) =
                        make_float2(v0, v1);
                }
            }
        }
    }
}

// ---------------- mask helper ----------------
__device__ __forceinline__ int keep_fn(int b, int l, const int* __restrict__ gm,
                                       const int* __restrict__ ta) {
    if (l < NQ) return 1;
    if (l < TS) return gm[b * NN + l - NQ];
    return ta[b * TT + l - TS];
}

// ============ fused flash attention (fp16, max-free softmax) ============
// grid (4 qtiles, 128 bh), 256 threads (8 warps, each owns 16 q rows).
// Per key tile kt: S = Q@K^T (Q frags in regs, K smem), mask+exp in regs,
// P fragments recycled directly as mma A operand, ctx += P@V (V via ldmatrix.trans).
// Epilogue: ctx * (1/rowsum) -> ctx16. No S materialization, no vT, no rsum buffer.
__global__ void __launch_bounds__(256) tc_flash_h(
    const __half* __restrict__ qkv, const int* __restrict__ gm,
    const int* __restrict__ ta, __half* __restrict__ ctx)
{
    extern __shared__ char smem[];
    const uint32_t sb = smem_u32(smem);
    const int tid = threadIdx.x;
    const int wid = tid >> 5, lane = tid & 31;
    const int bh = blockIdx.y, b = bh >> 3, h = bh & 7;
    const int mBase = blockIdx.x * 128;
    const int QS = 3 * DD;
    const int qrow0 = wid * 16;

    const __half* Aq  = qkv + (long)(b * LL + mBase) * QS + h * HD;
    const __half* Bk0 = qkv + (long)(b * LL) * QS + DD + h * HD;
    const __half* Vg  = qkv + (long)(b * LL) * QS + 2 * DD + h * HD;

    unsigned char* keepK = (unsigned char*)(smem + FKEEP_OFF);
    for (int i = tid; i < LL; i += 256) keepK[i] = (unsigned char)keep_fn(b, i, gm, ta);

    // ---- stage Q into V slot 0 (consumed into registers before V0 load) ----
    const uint32_t qb = sb + FV_OFF;
#pragma unroll
    for (int i = 0; i < 4; ++i) {
        int g = tid + i * 256, row = g >> 3, seg = g & 7;
        CP_ASYNC16(qb + swz128(row * 128 + seg * 16), Aq + (long)row * QS + seg * 8);
    }
#pragma unroll
    for (int i = 0; i < 2; ++i) {
        int g = tid + i * 256, row = g >> 2, seg = g & 3;
        CP_ASYNC16(qb + 16384 + swz64(row * 64 + seg * 16),
                   Aq + (long)row * QS + 64 + seg * 8);
    }
    CP_COMMIT();
    CP_WAIT0();
    __syncthreads();

    const int a_row = (lane & 7) + ((lane >> 3) & 1) * 8;
    const int a_seg = ((lane >> 4) & 1) * 16;
    uint32_t qf[6][4];
    {
        int row = qrow0 + a_row;
#pragma unroll
        for (int kq = 0; kq < 4; ++kq)
            LDSM_X4(qf[kq][0], qf[kq][1], qf[kq][2], qf[kq][3],
                    qb + swz128(row * 128 + kq * 32 + a_seg));
#pragma unroll
        for (int kq = 0; kq < 2; ++kq)
            LDSM_X4(qf[4 + kq][0], qf[4 + kq][1], qf[4 + kq][2], qf[4 + kq][3],
                    qb + 16384 + swz64(row * 64 + kq * 32 + a_seg));
    }
    __syncthreads();   // all warps done reading Q (V slot 0 now reusable)

    auto stage_kv = [&](int kt) {
        const uint32_t kb = sb + (kt % 3) * KSLOT;
        const uint32_t vb = sb + FV_OFF + (kt % 3) * VSLOT;
#pragma unroll
        for (int i = 0; i < 4; ++i) {
            int g = tid + i * 256, row = g >> 3, seg = g & 7;
            CP_ASYNC16(kb + swz128(row * 128 + seg * 16),
                       Bk0 + (long)(kt * 128 + row) * QS + seg * 8);
        }
#pragma unroll
        for (int i = 0; i < 2; ++i) {
            int g = tid + i * 256, row = g >> 2, seg = g & 3;
            CP_ASYNC16(kb + 16384 + swz64(row * 64 + seg * 16),
                       Bk0 + (long)(kt * 128 + row) * QS + 64 + seg * 8);
        }
        {
            int row = tid >> 1, hf = tid & 1;
#pragma unroll
            for (int c2 = 0; c2 < 6; ++c2) {
                int c = hf * 6 + c2;
                CP_ASYNC16(vb + row * VSTRIDE + c * 16,
                           Vg + (long)(kt * 128 + row) * QS + c * 8);
            }
        }
        CP_COMMIT();
    };
    stage_kv(0); stage_kv(1);

    const int b_row = (lane & 7) + ((lane >> 4) & 1) * 8;
    const int b_seg = ((lane >> 3) & 1) * 16;
    const int g4 = lane >> 2, t4 = lane & 3;
    const float scale = 0.10206207261596577f;   // 1/sqrt(96)

    float ctxa[12][4];
#pragma unroll
    for (int i = 0; i < 12; ++i)
#pragma unroll
        for (int r = 0; r < 4; ++r) ctxa[i][r] = 0.f;
    float rs0 = 0.f, rs1 = 0.f;

    const int q0g = mBase + qrow0 + g4;
    const int q1g = q0g + 8;
    const bool kq0 = keepK[q0g] != 0, kq1 = keepK[q1g] != 0;
    const bool qt0 = q0g >= TS, qt1 = q1g >= TS;

    for (int kt = 0; kt < 4; ++kt) {
        if (kt == 3) { CP_WAIT0(); } else { CP_WAIT1(); }
        __syncthreads();
        if (kt + 2 < 4) stage_kv(kt + 2);
        const uint32_t kb = sb + (kt % 3) * KSLOT;
        const uint32_t vb = sb + FV_OFF + (kt % 3) * VSLOT;

        // ---- S = Q @ K^T for this 128-key tile ----
        float sacc[16][4];
#pragma unroll
        for (int i = 0; i < 16; ++i)
#pragma unroll
            for (int r = 0; r < 4; ++r) sacc[i][r] = 0.f;
#pragma unroll
        for (int kq = 0; kq < 6; ++kq) {
#pragma unroll
            for (int nb = 0; nb < 8; ++nb) {
                int krow = nb * 16 + b_row;
                uint32_t addr = (kq < 4)
                    ? kb + swz128(krow * 128 + kq * 32 + b_seg)
                    : kb + 16384 + swz64(krow * 64 + (kq - 4) * 32 + b_seg);
                uint32_t v0, v1, v2, v3;
                LDSM_X4(v0, v1, v2, v3, addr);
                MMA_F16(sacc[2*nb][0], sacc[2*nb][1], sacc[2*nb][2], sacc[2*nb][3],
                        qf[kq][0], qf[kq][1], qf[kq][2], qf[kq][3], v0, v1);
                MMA_F16(sacc[2*nb+1][0], sacc[2*nb+1][1], sacc[2*nb+1][2], sacc[2*nb+1][3],
                        qf[kq][0], qf[kq][1], qf[kq][2], qf[kq][3], v2, v3);
            }
        }

        // ---- mask + exp + rowsum + pack into P A-fragments ----
        uint32_t pf[8][4];
#pragma unroll
        for (int ni = 0; ni < 16; ++ni) {
            int kbase = kt * 128 + ni * 8 + t4 * 2;
            float p[4];
#pragma unroll
            for (int r = 0; r < 4; ++r) {
                int k = kbase + (r & 1);
                bool ktk = k >= TS;
                bool kkk = keepK[k] != 0;
                bool qtr = (r < 2) ? qt0 : qt1;
                bool kqr = (r < 2) ? kq0 : kq1;
                int  qg  = (r < 2) ? q0g : q1g;
                bool ok = kqr && kkk && (!ktk || (qtr && qg >= k));
                p[r] = ok ? __expf(sacc[ni][r] * scale) : 0.f;
            }
            rs0 += p[0] + p[1];
            rs1 += p[2] + p[3];
            int jb = (ni & 1) * 2;
            pf[ni >> 1][jb]     = packh2(p[0], p[1]);
            pf[ni >> 1][jb + 1] = packh2(p[2], p[3]);
        }

        // ---- ctx += P @ V  (V via ldmatrix.trans from [key][d] rows) ----
        const int vtile = lane >> 3, vwi = lane & 7;
#pragma unroll
        for (int ki = 0; ki < 8; ++ki) {
#pragma unroll
            for (int db = 0; db < 3; ++db) {
                // two n16 blocks per db iteration (d = db*32 .. db*32+31)
#pragma unroll
                for (int half2b = 0; half2b < 2; ++half2b) {
                    int dblk = db * 2 + half2b;                  // n16 index 0..5
                    int key = ki * 16 + (vtile & 1) * 8 + vwi;
                    int dc = dblk * 16 + ((vtile >> 1) & 1) * 8;
                    uint32_t addr = vb + key * VSTRIDE + dc * 2;
                    uint32_t v0, v1, v2, v3;
                    LDSM_X4_T(v0, v1, v2, v3, addr);
                    int n0 = dblk * 2;
                    MMA_F16(ctxa[n0][0], ctxa[n0][1], ctxa[n0][2], ctxa[n0][3],
                            pf[ki][0], pf[ki][1], pf[ki][2], pf[ki][3], v0, v1);
                    MMA_F16(ctxa[n0+1][0], ctxa[n0+1][1], ctxa[n0+1][2], ctxa[n0+1][3],
                            pf[ki][0], pf[ki][1], pf[ki][2], pf[ki][3], v2, v3);
                }
            }
        }
    }

    // ---- rowsum reduce (within t4 quad) + epilogue ----
    rs0 += __shfl_xor_sync(0xffffffffu, rs0, 1);
    rs0 += __shfl_xor_sync(0xffffffffu, rs0, 2);
    rs1 += __shfl_xor_sync(0xffffffffu, rs1, 1);
    rs1 += __shfl_xor_sync(0xffffffffu, rs1, 2);
    float inv0 = 1.f / rs0, inv1 = 1.f / rs1;

    __half* C0 = ctx + (long)(b * LL + q0g) * DD + h * HD;
    __half* C1 = ctx + (long)(b * LL + q1g) * DD + h * HD;
#pragma unroll
    for (int db = 0; db < 12; ++db) {
        int d = db * 8 + t4 * 2;
        *(__half2*)(C0 + d) = __floats2half2_rn(ctxa[db][0] * inv0, ctxa[db][1] * inv0);
        *(__half2*)(C1 + d) = __floats2half2_rn(ctxa[db][2] * inv1, ctxa[db][3] * inv1);
    }
}

// ---------------- batched transpose to fp16: dst[z][C][R] = half(src[z][R][C]^T) ----------------
__global__ void __launch_bounds__(256) transpose_h_kernel(
    const float* __restrict__ src, __half* __restrict__ dst, int R, int C)
{
    __shared__ float t[32][33];
    long bo = (long)blockIdx.z * R * C;
    int x = blockIdx.x * 32 + threadIdx.x;
    int y = blockIdx.y * 32 + threadIdx.y;
#pragma unroll
    for (int i = 0; i < 32; i += 8)
        t[threadIdx.y + i][threadIdx.x] = src[bo + (long)(y + i) * C + x];
    __syncthreads();
    int x2 = blockIdx.y * 32 + threadIdx.x;
    int y2 = blockIdx.x * 32 + threadIdx.y;
#pragma unroll
    for (int i = 0; i < 32; i += 8)
        dst[bo + (long)(y2 + i) * R + x2] = __float2half(t[threadIdx.x][threadIdx.y + i]);
}

// ---------------- fp32 -> fp16 elementwise ----------------
__global__ void __launch_bounds__(256) conv16_kernel(
    const float* __restrict__ in, __half* __restrict__ out, long n)
{
    long i = (long)blockIdx.x * 256 + threadIdx.x;
    if (i < n) out[i] = __float2half(in[i]);
}

// ---------------- residual add + LayerNorm (fp32 x + fp16 x16 out) ----------------
__global__ void __launch_bounds__(256) add_ln_kernel(
    float* __restrict__ x, __half* __restrict__ x16, const float* __restrict__ delta,
    const float* __restrict__ pos, const float* __restrict__ tok,
    const float* __restrict__ g, const float* __restrict__ bt, int mode)
{
    __shared__ float sh[8];
    int row = blockIdx.x;
    int l = row & (LL - 1);
    int t = threadIdx.x, w = t >> 5, lane = t & 31;
    float* xr = x + (long)row * DD;
    float y[3];
#pragma unroll
    for (int i = 0; i < 3; ++i) {
        int d = t + i * 256;
        float v = xr[d];
        if (mode == 0) v += pos[l * DD + d] + tok[d];
        else           v += delta[(long)row * DD + d];
        y[i] = v;
    }
    float s = y[0] + y[1] + y[2];
#pragma unroll
    for (int o = 16; o; o >>= 1) s += __shfl_xor_sync(0xffffffffu, s, o);
    if (lane == 0) sh[w] = s;
    __syncthreads();
    s = sh[0] + sh[1] + sh[2] + sh[3] + sh[4] + sh[5] + sh[6] + sh[7];
    float mean = s * (1.f / DD);
    __syncthreads();
    float sq = 0.f;
#pragma unroll
    for (int i = 0; i < 3; ++i) { float d2 = y[i] - mean; sq += d2 * d2; }
#pragma unroll
    for (int o = 16; o; o >>= 1) sq += __shfl_xor_sync(0xffffffffu, sq, o);
    if (lane == 0) sh[w] = sq;
    __syncthreads();
    sq = sh[0] + sh[1] + sh[2] + sh[3] + sh[4] + sh[5] + sh[6] + sh[7];
    float rstd = rsqrtf(sq * (1.f / DD) + 1e-12f);
#pragma unroll
    for (int i = 0; i < 3; ++i) {
        int d = t + i * 256;
        float o = (y[i] - mean) * rstd * g[d] + bt[d];
        xr[d] = o;
        x16[(long)row * DD + d] = __float2half(o);
    }
}

// ---------------- assemble x = [queries | gfeat | text] ----------------
__global__ void __launch_bounds__(256) assemble_kernel(
    const float* __restrict__ qtok, const float* __restrict__ gfeat,
    const float* __restrict__ text, float* __restrict__ x)
{
    int row = blockIdx.x;
    int b = row >> 9, l = row & (LL - 1);
    int t = threadIdx.x;
    float* xr = x + (long)row * DD;
#pragma unroll
    for (int i = 0; i < 3; ++i) {
        int d = t + i * 256;
        float v;
        if (l < NQ)        v = qtok[l * DD + d];
        else if (l < TS)   v = gfeat[((long)(b * NN + l - NQ)) * DD + d];
        else               v = text[((long)(b * TT + l - TS)) * DD + d];
        xr[d] = v;
    }
}

// ---------------- output: text slice ----------------
__global__ void __launch_bounds__(256) output_kernel(const float* __restrict__ x,
                                                     float* __restrict__ out)
{
    long i = (long)blockIdx.x * 256 + threadIdx.x;
    const long total = (long)BB * TT * DD;
    if (i >= total) return;
    int d = (int)(i % DD);
    long r = i / DD;
    int tt = (int)(r % TT);
    int b  = (int)(r / TT);
    out[i] = x[((long)(b * LL + TS + tt)) * DD + d];
}

// ---------------- host orchestration ----------------
extern "C" void kernel_launch(void* const* d_in, const int* in_sizes, int n_in,
                              void* d_out, int out_size)
{
    const float* gnf     = (const float*)d_in[0];
    const float* text    = (const float*)d_in[1];
    const int*   ta      = (const int*)  d_in[2];
    const int*   gm      = (const int*)  d_in[3];
    const float* qtok    = (const float*)d_in[4];
    const float* gproj_w = (const float*)d_in[5];
    const float* gproj_b = (const float*)d_in[6];
    const float* pos     = (const float*)d_in[7];
    const float* tok     = (const float*)d_in[8];
    const float* eg      = (const float*)d_in[9];
    const float* eb      = (const float*)d_in[10];
    const float* qkv_w   = (const float*)d_in[11];
    const float* qkv_b   = (const float*)d_in[12];
    const float* ao_w    = (const float*)d_in[13];
    const float* ao_b    = (const float*)d_in[14];
    const float* ln1g    = (const float*)d_in[15];
    const float* ln1b    = (const float*)d_in[16];
    const float* ff1w    = (const float*)d_in[17];
    const float* ff1b    = (const float*)d_in[18];
    const float* ff2w    = (const float*)d_in[19];
    const float* ff2b    = (const float*)d_in[20];
    const float* ln2g    = (const float*)d_in[21];
    const float* ln2b    = (const float*)d_in[22];

    float *x, *y;
    __half *x16, *qkv16, *ctx16, *h16, *gnf16, *w16;
    cudaGetSymbolAddress((void**)&x,     g_x);
    cudaGetSymbolAddress((void**)&y,     g_y);
    cudaGetSymbolAddress((void**)&x16,   g_x16);
    cudaGetSymbolAddress((void**)&qkv16, g_qkv16);
    cudaGetSymbolAddress((void**)&ctx16, g_ctx16);
    cudaGetSymbolAddress((void**)&h16,   g_h16);
    cudaGetSymbolAddress((void**)&gnf16, g_gnf16);
    cudaGetSymbolAddress((void**)&w16,   g_w16);

    __half* qkvT   = w16 + WT_QKV;
    __half* aoT    = w16 + WT_AO;
    __half* ff1T   = w16 + WT_FF1;
    __half* ff2T   = w16 + WT_FF2;
    __half* gprojT = w16 + WT_GP;

    cudaFuncSetAttribute(tc_gemm_h, cudaFuncAttributeMaxDynamicSharedMemorySize, GSMEM_BYTES);
    cudaFuncSetAttribute(tc_flash_h, cudaFuncAttributeMaxDynamicSharedMemorySize, FSMEM_BYTES);

    dim3 tb(32, 8);
    // weight transposes into K-major fp16 B^T layouts
    transpose_h_kernel<<<dim3(2304/32, 768/32, 6), tb>>>(qkv_w, qkvT, 768, 2304);
    transpose_h_kernel<<<dim3(768/32,  768/32, 6), tb>>>(ao_w,  aoT,  768, 768);
    transpose_h_kernel<<<dim3(3072/32, 768/32, 6), tb>>>(ff1w,  ff1T, 768, 3072);
    transpose_h_kernel<<<dim3(768/32, 3072/32, 6), tb>>>(ff2w,  ff2T, 3072, 768);
    transpose_h_kernel<<<dim3(768/32,  768/32, 1), tb>>>(gproj_w, gprojT, 768, 768);
    conv16_kernel<<<(int)(((long)BB*NN*DD + 255) / 256), 256>>>(gnf, gnf16, (long)BB*NN*DD);

    // graph projection (fp32 out into y)
    tc_gemm_h<<<dim3(DD/128, (BB*NN)/128), 256, GSMEM_BYTES>>>(
        gnf16, gprojT, gproj_b, y, nullptr, BB*NN, DD, DD, 0);
    assemble_kernel<<<ROWS, 256>>>(qtok, y, text, x);
    add_ln_kernel<<<ROWS, 256>>>(x, x16, nullptr, pos, tok, eg, eb, 0);

    for (int i = 0; i < NLAY; ++i) {
        tc_gemm_h<<<dim3((3*DD)/128, ROWS/128), 256, GSMEM_BYTES>>>(
            x16, qkvT + (long)i * 2304 * 768, qkv_b + (long)i * 3 * DD,
            nullptr, qkv16, ROWS, 3*DD, DD, 0);
        tc_flash_h<<<dim3(LL/128, BB*HH), 256, FSMEM_BYTES>>>(qkv16, gm, ta, ctx16);
        tc_gemm_h<<<dim3(DD/128, ROWS/128), 256, GSMEM_BYTES>>>(
            ctx16, aoT + (long)i * 768 * 768, ao_b + (long)i * DD,
            y, nullptr, ROWS, DD, DD, 0);
        add_ln_kernel<<<ROWS, 256>>>(x, x16, y, nullptr, nullptr,
                                     ln1g + (long)i * DD, ln1b + (long)i * DD, 1);
        tc_gemm_h<<<dim3(FF/128, ROWS/128), 256, GSMEM_BYTES>>>(
            x16, ff1T + (long)i * 3072 * 768, ff1b + (long)i * FF,
            nullptr, h16, ROWS, FF, DD, 1);
        tc_gemm_h<<<dim3(DD/128, ROWS/128), 256, GSMEM_BYTES>>>(
            h16, ff2T + (long)i * 768 * 3072, ff2b + (long)i * DD,
            y, nullptr, ROWS, DD, FF, 0);
        add_ln_kernel<<<ROWS, 256>>>(x, x16, y, nullptr, nullptr,
                                     ln2g + (long)i * DD, ln2b + (long)i * DD, 1);
    }

    long total = (long)BB * TT * DD;
    output_kernel<<<(int)((total + 255) / 256), 256>>>(x, (float*)d_out);
}